// round 9
// baseline (speedup 1.0000x reference)
#include <cuda_runtime.h>
#include <cuda_fp16.h>
#include <cstdint>

#define BB 2048
#define SS 288
#define HH 512
#define TT 144
#define G4 (4*HH)

#define NBLK 128
#define NTHR 1024
#define BM 128
#define BNJ 64          // j-cols per block
#define BK 64
#define NGRP 16         // M-row groups
#define GBLK 8          // blocks per group (N-partition)

#define STG_A_SZ (BM*128)            // 16 KB
#define STG_B_SZ (256*128)           // 32 KB
#define STG_SZ   (STG_A_SZ+STG_B_SZ) // 48 KB
#define SMEM_DYN (3*STG_SZ + 1024)

#define SW128(x) ((x) ^ (((x) >> 3) & 0x70))

// ---------------- device state (static; no runtime allocation) ----------------
__device__ __align__(128) __half g_hA[BB*1024];       // [h0 | h1] ping
__device__ __align__(128) __half g_hB[BB*1024];       // [h0 | h1] pong
__device__ __align__(128) float  g_c0[BB*HH];
__device__ __align__(128) float  g_c1[BB*HH];
__device__ __align__(128) float  g_pred[BB];
__device__ __align__(128) float  g_predPart[64*BB];
__device__ __align__(128) __half g_encW0[G4*HH];
__device__ __align__(128) __half g_encW1[G4*2*HH];
__device__ __align__(128) __half g_decW0[G4*HH];
__device__ __align__(128) __half g_decW1[G4*2*HH];
__device__ __align__(128) float  g_encB0[G4];
__device__ __align__(128) float  g_encB1[G4];
__device__ __align__(128) float  g_decB0[G4];
__device__ __align__(128) float  g_decB1[G4];
__device__ unsigned g_grpCnt[NGRP];
__device__ unsigned g_grpGen[NGRP];
__device__ unsigned g_barCnt;
__device__ unsigned g_barGen;

// ---------------- barriers ----------------
__device__ __forceinline__ void group_barrier(int grp, unsigned &gen){
    __threadfence();
    __syncthreads();
    if (threadIdx.x == 0){
        unsigned prev = atomicAdd(&g_grpCnt[grp], 1u);
        if (prev == GBLK - 1u){
            *(volatile unsigned*)&g_grpCnt[grp] = 0u;
            __threadfence();
            *(volatile unsigned*)&g_grpGen[grp] = gen + 1u;
        } else {
            while (*(volatile unsigned*)&g_grpGen[grp] == gen) __nanosleep(32);
        }
    }
    __syncthreads();
    __threadfence();
    gen++;
}
__device__ __forceinline__ void grid_barrier(unsigned &gen){
    __threadfence();
    __syncthreads();
    if (threadIdx.x == 0){
        unsigned prev = atomicAdd(&g_barCnt, 1u);
        if (prev == NBLK - 1u){
            *(volatile unsigned*)&g_barCnt = 0u;
            __threadfence();
            *(volatile unsigned*)&g_barGen = gen + 1u;
        } else {
            while (*(volatile unsigned*)&g_barGen == gen) __nanosleep(64);
        }
    }
    __syncthreads();
    __threadfence();
    gen++;
}

// ---------------- helpers ----------------
__device__ __forceinline__ void cp16(unsigned d, const void* s){
    asm volatile("cp.async.cg.shared.global [%0], [%1], 16;\n" :: "r"(d), "l"(s));
}
__device__ __forceinline__ void cp_commit(){ asm volatile("cp.async.commit_group;\n"); }
__device__ __forceinline__ void cp_wait1(){ asm volatile("cp.async.wait_group 1;\n"); }
__device__ __forceinline__ void cp_wait0(){ asm volatile("cp.async.wait_group 0;\n"); }

__device__ __forceinline__ void ldsm_x4(unsigned* r, unsigned a){
    asm volatile("ldmatrix.sync.aligned.m8n8.x4.shared.b16 {%0,%1,%2,%3}, [%4];\n"
        : "=r"(r[0]), "=r"(r[1]), "=r"(r[2]), "=r"(r[3]) : "r"(a));
}
__device__ __forceinline__ void mma16816(float* d, const unsigned* a, unsigned b0, unsigned b1){
    asm volatile(
        "mma.sync.aligned.m16n8k16.row.col.f32.f16.f16.f32 "
        "{%0,%1,%2,%3}, {%4,%5,%6,%7}, {%8,%9}, {%0,%1,%2,%3};\n"
        : "+f"(d[0]), "+f"(d[1]), "+f"(d[2]), "+f"(d[3])
        : "r"(a[0]), "r"(a[1]), "r"(a[2]), "r"(a[3]), "r"(b0), "r"(b1));
}

// ---- fast activations: single-MUFU tanh (sm_75+) ----
__device__ __forceinline__ float tanh_fast(float x){
    float y;
    asm("tanh.approx.f32 %0, %1;\n" : "=f"(y) : "f"(x));
    return y;
}
__device__ __forceinline__ float sig_fast(float x){
    return fmaf(tanh_fast(0.5f * x), 0.5f, 0.5f);
}

// ---------------- one fused GEMM + LSTM-cell phase ----------------
// B smem row n (0..255):  wjIdx = n>>5, gate = (n>>3)&3, jo = n&7
//   <- W row  gate*HH + jBase + wjIdx*8 + jo
// Warp (wm, wjIdx) computes D[wm..wm+32, n=wjIdx*32..+32]: its 32 N-cols are
// 4 gate-chunks of 8 j's -> every thread owns all 4 gates of its j's.
__device__ void step_layer(char* smb, int bx, int by, int tid, int warp, int lane,
    const __half* __restrict__ A0, const __half* __restrict__ A1,
    const __half* __restrict__ W, int K,
    const float* __restrict__ bias, const float* __restrict__ w0,
    const float* __restrict__ xsrc, int xstride,
    float* __restrict__ cbuf, __half* __restrict__ hOut,
    bool hasX, bool doFC, const float* __restrict__ fcW)
{
    const int gmBase = bx * BM;
    const int jBase  = by * BNJ;
    const int nT = K / BK;

    float acc[2][4][4];   // [mt][gate][r]
    #pragma unroll
    for (int a = 0; a < 2; a++)
        #pragma unroll
        for (int g = 0; g < 4; g++)
            #pragma unroll
            for (int r = 0; r < 4; r++) acc[a][g][r] = 0.f;

    const int wm    = (warp & 3) * 32;     // 4 warps over M=128
    const int wjIdx = warp >> 2;           // 8 warps over N=256 (8 j's each)
    const int lr = lane >> 2;
    const int lc = lane & 3;

    const int l8  = lane & 7;
    const int seg = lane >> 3;
    const int aRowOff = ((seg & 1) ? 8 : 0) + l8;   // A regs: (m0,k0),(m8,k0),(m0,k8),(m8,k8)
    const int aColOff = (seg >> 1) ? 8 : 0;
    const int bRowOff = ((seg >> 1) ? 8 : 0) + l8;  // B regs: (n0,k0),(n0,k8),(n8,k0),(n8,k8)
    const int bColOff = (seg & 1) ? 8 : 0;

    const unsigned smbase = (unsigned)__cvta_generic_to_shared(smb);

    // ---- hoisted LDSM address math ----
    // SW128(row*128 + col) = row*128 + (col ^ mask), mask = ((row*128)>>3)&0x70,
    // and col = colOff2(bit4) + ks*32(bits5-6) splits: addr = base + (ks*32 ^ maskHi).
    unsigned aBase[2], aMaskHi[2];
    #pragma unroll
    for (int mt = 0; mt < 2; mt++){
        const unsigned rowT = (unsigned)((wm + mt*16 + aRowOff) * 128);
        const unsigned mask = (rowT >> 3) & 0x70u;
        aBase[mt]  = rowT + ((unsigned)(aColOff*2) ^ (mask & 0x10u));
        aMaskHi[mt] = mask & 0x60u;
    }
    unsigned bBase[2], bMaskHi[2];
    #pragma unroll
    for (int nh = 0; nh < 2; nh++){
        const unsigned rowT = (unsigned)((wjIdx*32 + nh*16 + bRowOff) * 128);
        const unsigned mask = (rowT >> 3) & 0x70u;
        bBase[nh]  = (unsigned)STG_A_SZ + rowT + ((unsigned)(bColOff*2) ^ (mask & 0x10u));
        bMaskHi[nh] = mask & 0x60u;
    }

    // ---- hoisted cp.async mappings ----
    const int ar = tid >> 3, acs = tid & 7;
    const unsigned adstOff = SW128((unsigned)(ar*128 + acs*16));
    const size_t aSrcElem = (size_t)(gmBase + ar) * 1024 + acs*8;
    unsigned bdstOff[2];
    const __half* bsrcBase[2];
    #pragma unroll
    for (int i = 0; i < 2; i++){
        const int q = tid + i*NTHR;
        const int r = q >> 3, cc = q & 7;
        const int wr = ((r >> 3) & 3)*HH + jBase + ((r >> 5) << 3) + (r & 7);
        bdstOff[i] = (unsigned)STG_A_SZ + SW128((unsigned)(r*128 + cc*16));
        bsrcBase[i] = W + (size_t)wr*K + cc*8;
    }

    auto issue = [&](int tt){
        const unsigned st = smbase + (unsigned)((tt % 3) * STG_SZ);
        const int kk = tt * BK;
        const __half* Ap = (kk < HH) ? (A0 + kk) : (A1 + (kk - HH));
        cp16(st + adstOff, Ap + aSrcElem);
        cp16(st + bdstOff[0], bsrcBase[0] + kk);
        cp16(st + bdstOff[1], bsrcBase[1] + kk);
        cp_commit();
    };

    issue(0);
    issue(1);
    for (int tt = 0; tt < nT; tt++){
        if (tt + 2 < nT) cp_wait1(); else cp_wait0();
        __syncthreads();
        if (tt + 2 < nT) issue(tt + 2);
        const unsigned st = smbase + (unsigned)((tt % 3) * STG_SZ);
        #pragma unroll
        for (int ks = 0; ks < 4; ks++){
            const unsigned ks32 = (unsigned)(ks * 32);
            unsigned a[2][4];
            #pragma unroll
            for (int mt = 0; mt < 2; mt++)
                ldsm_x4(a[mt], st + aBase[mt] + (ks32 ^ aMaskHi[mt]));
            unsigned bl[4], bh[4];
            ldsm_x4(bl, st + bBase[0] + (ks32 ^ bMaskHi[0]));
            ldsm_x4(bh, st + bBase[1] + (ks32 ^ bMaskHi[1]));
            #pragma unroll
            for (int mt = 0; mt < 2; mt++){
                mma16816(acc[mt][0], a[mt], bl[0], bl[1]);
                mma16816(acc[mt][1], a[mt], bl[2], bl[3]);
                mma16816(acc[mt][2], a[mt], bh[0], bh[1]);
                mma16816(acc[mt][3], a[mt], bh[2], bh[3]);
            }
        }
    }
    __syncthreads();   // protect smem before next phase reuses it

    // ------- fused LSTM epilogue (tanh.approx activations) -------
    const int j0 = jBase + wjIdx*8;
    float fcs[4] = {0.f, 0.f, 0.f, 0.f};
    #pragma unroll
    for (int mt = 0; mt < 2; mt++){
        #pragma unroll
        for (int rr = 0; rr < 2; rr++){
            const int m = gmBase + wm + mt*16 + lr + rr*8;
            const float xval = hasX ? xsrc[(size_t)m * xstride] : 0.f;
            #pragma unroll
            for (int jj = 0; jj < 2; jj++){
                const int j = j0 + 2*lc + jj;
                const int r = rr*2 + jj;
                float gi = acc[mt][0][r] + bias[j];
                float gf = acc[mt][1][r] + bias[HH + j];
                float gg = acc[mt][2][r] + bias[2*HH + j];
                float go = acc[mt][3][r] + bias[3*HH + j];
                if (hasX){
                    gi += xval * w0[j];
                    gf += xval * w0[HH + j];
                    gg += xval * w0[2*HH + j];
                    go += xval * w0[3*HH + j];
                }
                const float c  = cbuf[(size_t)m*HH + j];
                const float cn = sig_fast(gf)*c + sig_fast(gi)*tanh_fast(gg);
                const float hn = sig_fast(go)*tanh_fast(cn);
                cbuf[(size_t)m*HH + j] = cn;
                hOut[(size_t)m*1024 + j] = __float2half(hn);
                if (doFC) fcs[mt*2 + rr] += hn * fcW[j];
            }
        }
    }
    if (doFC){
        #pragma unroll
        for (int i = 0; i < 4; i++){
            fcs[i] += __shfl_xor_sync(0xffffffffu, fcs[i], 1);
            fcs[i] += __shfl_xor_sync(0xffffffffu, fcs[i], 2);
        }
        if (lc == 0){
            const int partIdx = by*8 + wjIdx;       // 64 partials per row
            #pragma unroll
            for (int i = 0; i < 4; i++){
                const int m = gmBase + wm + (i >> 1)*16 + lr + ((i & 1) ? 8 : 0);
                g_predPart[partIdx*BB + m] = fcs[i];
            }
        }
    }
}

// ---------------- the single persistent kernel ----------------
__global__ void __launch_bounds__(NTHR, 1)
seq2seq_persistent(const float* __restrict__ x,
    const float* __restrict__ eWih0, const float* __restrict__ eWhh0,
    const float* __restrict__ ebih0, const float* __restrict__ ebhh0,
    const float* __restrict__ eWih1, const float* __restrict__ eWhh1,
    const float* __restrict__ ebih1, const float* __restrict__ ebhh1,
    const float* __restrict__ dWih0, const float* __restrict__ dWhh0,
    const float* __restrict__ dbih0, const float* __restrict__ dbhh0,
    const float* __restrict__ dWih1, const float* __restrict__ dWhh1,
    const float* __restrict__ dbih1, const float* __restrict__ dbhh1,
    const float* __restrict__ fcW,  const float* __restrict__ fcb,
    float* __restrict__ out)
{
    extern __shared__ char smraw[];
    char* smb = (char*)(((uintptr_t)smraw + 1023) & ~(uintptr_t)1023);

    const int tid  = threadIdx.x;
    const int warp = tid >> 5;
    const int lane = tid & 31;
    const int blk  = blockIdx.x;
    const int bx   = blk & 15;          // M-group (16 of 128 rows)
    const int by   = blk >> 4;          // N-partition within group (8 of 64 j)
    const int gtid = blk * NTHR + tid;
    const int NT   = NBLK * NTHR;

    unsigned ggen = *(volatile unsigned*)&g_barGen;

    // ---- prep: zero state, pack weights to fp16, combine biases ----
    for (int i = gtid; i < BB*1024; i += NT) g_hA[i] = __float2half(0.f);
    for (int i = gtid; i < BB*HH; i += NT){ g_c0[i] = 0.f; g_c1[i] = 0.f; }
    for (int i = gtid; i < G4*HH; i += NT){
        g_encW0[i] = __float2half(eWhh0[i]);
        g_decW0[i] = __float2half(dWhh0[i]);
    }
    for (int i = gtid; i < G4*1024; i += NT){
        const int n = i >> 10, k = i & 1023;
        g_encW1[i] = __float2half((k < HH) ? eWih1[n*HH + k] : eWhh1[n*HH + k - HH]);
        g_decW1[i] = __float2half((k < HH) ? dWih1[n*HH + k] : dWhh1[n*HH + k - HH]);
    }
    if (gtid < G4){
        g_encB0[gtid] = ebih0[gtid] + ebhh0[gtid];
        g_encB1[gtid] = ebih1[gtid] + ebhh1[gtid];
        g_decB0[gtid] = dbih0[gtid] + dbhh0[gtid];
        g_decB1[gtid] = dbih1[gtid] + dbhh1[gtid];
    }
    grid_barrier(ggen);

    unsigned gen = *(volatile unsigned*)&g_grpGen[bx];

    __half* cur = g_hA;
    __half* nxt = g_hB;

    for (int t = 0; t < SS + TT; t++){
        const bool dec = (t >= SS);
        const __half* W0 = dec ? g_decW0 : g_encW0;
        const __half* W1 = dec ? g_decW1 : g_encW1;
        const float* B0  = dec ? g_decB0 : g_encB0;
        const float* B1  = dec ? g_decB1 : g_encB1;
        const float* w0  = dec ? dWih0 : eWih0;

        const float* xs;
        int xstr;
        if (!dec)          { xs = x + t;        xstr = SS; }
        else if (t == SS)  { xs = x + (SS - 1); xstr = SS; }
        else               { xs = g_pred;       xstr = 1;  }

        // layer 0
        step_layer(smb, bx, by, tid, warp, lane, cur, (const __half*)nullptr, W0, HH,
                   B0, w0, xs, xstr, g_c0, nxt, true, false, nullptr);
        group_barrier(bx, gen);

        // layer 1 (+ FC partials in decoder)
        step_layer(smb, bx, by, tid, warp, lane, nxt, cur + HH, W1, 2*HH,
                   B1, nullptr, nullptr, 0, g_c1, nxt + HH, false, dec, fcW);
        group_barrier(bx, gen);

        if (dec){
            if (by == 0 && tid < BM){
                const int m = bx * BM + tid;
                float s = fcb[0];
                #pragma unroll
                for (int p = 0; p < 64; p++) s += g_predPart[p*BB + m];
                g_pred[m] = s;
                out[(size_t)m*TT + (t - SS)] = s;
            }
            group_barrier(bx, gen);
        }

        __half* tmp = cur; cur = nxt; nxt = tmp;
    }
}

// ---------------- host: one launch, one graph node ----------------
extern "C" void kernel_launch(void* const* d_in, const int* in_sizes, int n_in,
                              void* d_out, int out_size)
{
    cudaFuncSetAttribute((const void*)seq2seq_persistent,
                         cudaFuncAttributeMaxDynamicSharedMemorySize, SMEM_DYN);

    seq2seq_persistent<<<NBLK, NTHR, SMEM_DYN>>>(
        (const float*)d_in[0],
        (const float*)d_in[1],  (const float*)d_in[2],
        (const float*)d_in[3],  (const float*)d_in[4],
        (const float*)d_in[5],  (const float*)d_in[6],
        (const float*)d_in[7],  (const float*)d_in[8],
        (const float*)d_in[9],  (const float*)d_in[10],
        (const float*)d_in[11], (const float*)d_in[12],
        (const float*)d_in[13], (const float*)d_in[14],
        (const float*)d_in[15], (const float*)d_in[16],
        (const float*)d_in[17], (const float*)d_in[18],
        (float*)d_out);
    (void)in_sizes; (void)n_in; (void)out_size;
}

// round 11
// speedup vs baseline: 1.1150x; 1.1150x over previous
#include <cuda_runtime.h>
#include <cuda_fp16.h>
#include <cstdint>

#define BB 2048
#define SS 288
#define HH 512
#define TT 144
#define G4 (4*HH)

#define NBLK 128
#define NTHR 512
#define BM 128
#define BNJ 64          // j-cols per block
#define BK 64
#define NGRP 16         // M-row groups
#define GBLK 8          // blocks per group (N-partition)

#define STG_A_SZ (BM*128)            // 16 KB
#define STG_B_SZ (256*128)           // 32 KB
#define STG_SZ   (STG_A_SZ+STG_B_SZ) // 48 KB
#define SMEM_DYN (3*STG_SZ + 1024)

#define SW128(x) ((x) ^ (((x) >> 3) & 0x70))

// ---------------- device state (static; no runtime allocation) ----------------
__device__ __align__(128) __half g_hA[BB*1024];       // [h0 | h1] ping
__device__ __align__(128) __half g_hB[BB*1024];       // [h0 | h1] pong
__device__ __align__(128) float  g_c0[BB*HH];
__device__ __align__(128) float  g_c1[BB*HH];
__device__ __align__(128) float  g_pred[BB];
__device__ __align__(128) float  g_predPart[64*BB];
__device__ __align__(128) __half g_encW0[G4*HH];
__device__ __align__(128) __half g_encW1[G4*2*HH];
__device__ __align__(128) __half g_decW0[G4*HH];
__device__ __align__(128) __half g_decW1[G4*2*HH];
__device__ __align__(128) float  g_encB0[G4];
__device__ __align__(128) float  g_encB1[G4];
__device__ __align__(128) float  g_decB0[G4];
__device__ __align__(128) float  g_decB1[G4];
__device__ unsigned g_grpCnt[NGRP];
__device__ unsigned g_grpGen[NGRP];
__device__ unsigned g_barCnt;
__device__ unsigned g_barGen;

// ---------------- barriers ----------------
__device__ __forceinline__ void group_barrier(int grp, unsigned &gen){
    __threadfence();
    __syncthreads();
    if (threadIdx.x == 0){
        unsigned prev = atomicAdd(&g_grpCnt[grp], 1u);
        if (prev == GBLK - 1u){
            *(volatile unsigned*)&g_grpCnt[grp] = 0u;
            __threadfence();
            *(volatile unsigned*)&g_grpGen[grp] = gen + 1u;
        } else {
            while (*(volatile unsigned*)&g_grpGen[grp] == gen) __nanosleep(32);
        }
    }
    __syncthreads();
    __threadfence();
    gen++;
}
__device__ __forceinline__ void grid_barrier(unsigned &gen){
    __threadfence();
    __syncthreads();
    if (threadIdx.x == 0){
        unsigned prev = atomicAdd(&g_barCnt, 1u);
        if (prev == NBLK - 1u){
            *(volatile unsigned*)&g_barCnt = 0u;
            __threadfence();
            *(volatile unsigned*)&g_barGen = gen + 1u;
        } else {
            while (*(volatile unsigned*)&g_barGen == gen) __nanosleep(64);
        }
    }
    __syncthreads();
    __threadfence();
    gen++;
}

// ---------------- helpers ----------------
__device__ __forceinline__ void cp16(unsigned d, const void* s){
    asm volatile("cp.async.cg.shared.global [%0], [%1], 16;\n" :: "r"(d), "l"(s));
}
__device__ __forceinline__ void cp_commit(){ asm volatile("cp.async.commit_group;\n"); }
__device__ __forceinline__ void cp_wait1(){ asm volatile("cp.async.wait_group 1;\n"); }
__device__ __forceinline__ void cp_wait0(){ asm volatile("cp.async.wait_group 0;\n"); }

__device__ __forceinline__ void ldsm_x4(unsigned* r, const void* p){
    unsigned a = (unsigned)__cvta_generic_to_shared(p);
    asm volatile("ldmatrix.sync.aligned.m8n8.x4.shared.b16 {%0,%1,%2,%3}, [%4];\n"
        : "=r"(r[0]), "=r"(r[1]), "=r"(r[2]), "=r"(r[3]) : "r"(a));
}
__device__ __forceinline__ void mma16816(float* d, const unsigned* a, unsigned b0, unsigned b1){
    asm volatile(
        "mma.sync.aligned.m16n8k16.row.col.f32.f16.f16.f32 "
        "{%0,%1,%2,%3}, {%4,%5,%6,%7}, {%8,%9}, {%0,%1,%2,%3};\n"
        : "+f"(d[0]), "+f"(d[1]), "+f"(d[2]), "+f"(d[3])
        : "r"(a[0]), "r"(a[1]), "r"(a[2]), "r"(a[3]), "r"(b0), "r"(b1));
}
__device__ __forceinline__ float sigf(float x){
    return __fdividef(1.f, 1.f + __expf(-x));
}
__device__ __forceinline__ float tanh_f(float x){
    float t = __expf(-2.f * fabsf(x));
    float r = __fdividef(1.f - t, 1.f + t);
    return copysignf(r, x);
}

// ---------------- one fused GEMM + LSTM-cell phase ----------------
// B smem row n (0..255):  wjIdx = n>>5, gate = (n>>3)&3, jo = n&7
//   <- W row  gate*HH + jBase + wjIdx*8 + jo
// 16 warps: wmIdx = warp&1 (M half, 64 rows via 4 m-tiles), wjIdx = warp>>1
// (8 N-strips of 32 = 4 gates x 8 j). Each thread owns all 4 gates of its j's.
__device__ void step_layer(char* smb, int bx, int by, int tid, int warp, int lane,
    const __half* __restrict__ A0, const __half* __restrict__ A1,
    const __half* __restrict__ W, int K,
    const float* __restrict__ bias, const float* __restrict__ w0,
    const float* __restrict__ xsrc, int xstride,
    float* __restrict__ cbuf, __half* __restrict__ hOut,
    bool hasX, bool doFC, const float* __restrict__ fcW)
{
    const int gmBase = bx * BM;
    const int jBase  = by * BNJ;
    const int nT = K / BK;

    float acc[4][4][4];   // [mt][gate][r]
    #pragma unroll
    for (int a = 0; a < 4; a++)
        #pragma unroll
        for (int g = 0; g < 4; g++)
            #pragma unroll
            for (int r = 0; r < 4; r++) acc[a][g][r] = 0.f;

    const int wm    = (warp & 1) * 64;     // 2 warps over M=128 (64 rows each)
    const int wjIdx = warp >> 1;           // 8 warps over N=256 (8 j's each)
    const int lr = lane >> 2;
    const int lc = lane & 3;

    const int l8  = lane & 7;
    const int seg = lane >> 3;
    const int aRowOff = ((seg & 1) ? 8 : 0) + l8;   // A regs: (m0,k0),(m8,k0),(m0,k8),(m8,k8)
    const int aColOff = (seg >> 1) ? 8 : 0;
    const int bRowOff = ((seg >> 1) ? 8 : 0) + l8;  // B regs: (n0,k0),(n0,k8),(n8,k0),(n8,k8)
    const int bColOff = (seg & 1) ? 8 : 0;

    auto issue = [&](int tt){
        const int s = tt % 3;
        const unsigned stA = (unsigned)__cvta_generic_to_shared(smb + s*STG_SZ);
        const unsigned stB = stA + STG_A_SZ;
        const int kk = tt * BK;
        const __half* Ap = (kk < HH) ? (A0 + kk) : (A1 + (kk - HH));
        #pragma unroll
        for (int i = 0; i < 2; i++){   // A: 128 rows x 128B, 2 cp16/thread
            const int q = tid + i*NTHR;
            const int r = q >> 3, cc = q & 7;
            cp16(stA + SW128(r*128 + cc*16), Ap + (size_t)(gmBase + r)*1024 + cc*8);
        }
        #pragma unroll
        for (int i = 0; i < 4; i++){   // B: 256 rows x 128B, 4 cp16/thread
            const int q = tid + i*NTHR;
            const int r = q >> 3, cc = q & 7;
            const int wr = ((r >> 3) & 3)*HH + jBase + ((r >> 5) << 3) + (r & 7);
            cp16(stB + SW128(r*128 + cc*16), W + (size_t)wr*K + kk + cc*8);
        }
        cp_commit();
    };

    issue(0);
    issue(1);
    for (int tt = 0; tt < nT; tt++){
        if (tt + 2 < nT) cp_wait1(); else cp_wait0();
        __syncthreads();
        if (tt + 2 < nT) issue(tt + 2);
        const int s = tt % 3;
        const char* Ab = smb + s*STG_SZ;
        const char* Bb = smb + s*STG_SZ + STG_A_SZ;
        #pragma unroll
        for (int ks = 0; ks < 4; ks++){
            const int kb = ks * 16;
            unsigned a[4][4];
            #pragma unroll
            for (int mt = 0; mt < 4; mt++){
                const unsigned off = SW128((unsigned)((wm + mt*16 + aRowOff)*128 + (kb + aColOff)*2));
                ldsm_x4(a[mt], Ab + off);
            }
            unsigned bl[4], bh[4];
            {
                const unsigned offL = SW128((unsigned)((wjIdx*32 + bRowOff)*128 + (kb + bColOff)*2));
                const unsigned offH = SW128((unsigned)((wjIdx*32 + 16 + bRowOff)*128 + (kb + bColOff)*2));
                ldsm_x4(bl, Bb + offL);
                ldsm_x4(bh, Bb + offH);
            }
            #pragma unroll
            for (int mt = 0; mt < 4; mt++){
                mma16816(acc[mt][0], a[mt], bl[0], bl[1]);
                mma16816(acc[mt][1], a[mt], bl[2], bl[3]);
                mma16816(acc[mt][2], a[mt], bh[0], bh[1]);
                mma16816(acc[mt][3], a[mt], bh[2], bh[3]);
            }
        }
    }
    __syncthreads();   // protect smem before next phase reuses it

    // ------- fused LSTM epilogue -------
    const int j0 = jBase + wjIdx*8;
    float fcs[8] = {0.f, 0.f, 0.f, 0.f, 0.f, 0.f, 0.f, 0.f};
    #pragma unroll
    for (int mt = 0; mt < 4; mt++){
        #pragma unroll
        for (int rr = 0; rr < 2; rr++){
            const int m = gmBase + wm + mt*16 + lr + rr*8;
            const float xval = hasX ? xsrc[(size_t)m * xstride] : 0.f;
            #pragma unroll
            for (int jj = 0; jj < 2; jj++){
                const int j = j0 + 2*lc + jj;
                const int r = rr*2 + jj;
                float gi = acc[mt][0][r] + bias[j];
                float gf = acc[mt][1][r] + bias[HH + j];
                float gg = acc[mt][2][r] + bias[2*HH + j];
                float go = acc[mt][3][r] + bias[3*HH + j];
                if (hasX){
                    gi += xval * w0[j];
                    gf += xval * w0[HH + j];
                    gg += xval * w0[2*HH + j];
                    go += xval * w0[3*HH + j];
                }
                const float c  = cbuf[(size_t)m*HH + j];
                const float cn = sigf(gf)*c + sigf(gi)*tanh_f(gg);
                const float hn = sigf(go)*tanh_f(cn);
                cbuf[(size_t)m*HH + j] = cn;
                hOut[(size_t)m*1024 + j] = __float2half(hn);
                if (doFC) fcs[mt*2 + rr] += hn * fcW[j];
            }
        }
    }
    if (doFC){
        #pragma unroll
        for (int i = 0; i < 8; i++){
            fcs[i] += __shfl_xor_sync(0xffffffffu, fcs[i], 1);
            fcs[i] += __shfl_xor_sync(0xffffffffu, fcs[i], 2);
        }
        if (lc == 0){
            const int partIdx = by*8 + wjIdx;       // 64 partials per row
            #pragma unroll
            for (int i = 0; i < 8; i++){
                const int m = gmBase + wm + (i >> 1)*16 + lr + ((i & 1) ? 8 : 0);
                g_predPart[partIdx*BB + m] = fcs[i];
            }
        }
    }
}

// ---------------- the single persistent kernel ----------------
__global__ void __launch_bounds__(NTHR, 1)
seq2seq_persistent(const float* __restrict__ x,
    const float* __restrict__ eWih0, const float* __restrict__ eWhh0,
    const float* __restrict__ ebih0, const float* __restrict__ ebhh0,
    const float* __restrict__ eWih1, const float* __restrict__ eWhh1,
    const float* __restrict__ ebih1, const float* __restrict__ ebhh1,
    const float* __restrict__ dWih0, const float* __restrict__ dWhh0,
    const float* __restrict__ dbih0, const float* __restrict__ dbhh0,
    const float* __restrict__ dWih1, const float* __restrict__ dWhh1,
    const float* __restrict__ dbih1, const float* __restrict__ dbhh1,
    const float* __restrict__ fcW,  const float* __restrict__ fcb,
    float* __restrict__ out)
{
    extern __shared__ char smraw[];
    char* smb = (char*)(((uintptr_t)smraw + 1023) & ~(uintptr_t)1023);

    const int tid  = threadIdx.x;
    const int warp = tid >> 5;
    const int lane = tid & 31;
    const int blk  = blockIdx.x;
    const int bx   = blk & 15;          // M-group (16 of 128 rows)
    const int by   = blk >> 4;          // N-partition within group (8 of 64 j)
    const int gtid = blk * NTHR + tid;
    const int NT   = NBLK * NTHR;

    unsigned ggen = *(volatile unsigned*)&g_barGen;

    // ---- prep: zero state, pack weights to fp16, combine biases ----
    for (int i = gtid; i < BB*1024; i += NT) g_hA[i] = __float2half(0.f);
    for (int i = gtid; i < BB*HH; i += NT){ g_c0[i] = 0.f; g_c1[i] = 0.f; }
    for (int i = gtid; i < G4*HH; i += NT){
        g_encW0[i] = __float2half(eWhh0[i]);
        g_decW0[i] = __float2half(dWhh0[i]);
    }
    for (int i = gtid; i < G4*1024; i += NT){
        const int n = i >> 10, k = i & 1023;
        g_encW1[i] = __float2half((k < HH) ? eWih1[n*HH + k] : eWhh1[n*HH + k - HH]);
        g_decW1[i] = __float2half((k < HH) ? dWih1[n*HH + k] : dWhh1[n*HH + k - HH]);
    }
    if (gtid < G4){
        g_encB0[gtid] = ebih0[gtid] + ebhh0[gtid];
        g_encB1[gtid] = ebih1[gtid] + ebhh1[gtid];
        g_decB0[gtid] = dbih0[gtid] + dbhh0[gtid];
        g_decB1[gtid] = dbih1[gtid] + dbhh1[gtid];
    }
    grid_barrier(ggen);

    unsigned gen = *(volatile unsigned*)&g_grpGen[bx];

    __half* cur = g_hA;
    __half* nxt = g_hB;

    for (int t = 0; t < SS + TT; t++){
        const bool dec = (t >= SS);
        const __half* W0 = dec ? g_decW0 : g_encW0;
        const __half* W1 = dec ? g_decW1 : g_encW1;
        const float* B0  = dec ? g_decB0 : g_encB0;
        const float* B1  = dec ? g_decB1 : g_encB1;
        const float* w0  = dec ? dWih0 : eWih0;

        const float* xs;
        int xstr;
        if (!dec)          { xs = x + t;        xstr = SS; }
        else if (t == SS)  { xs = x + (SS - 1); xstr = SS; }
        else               { xs = g_pred;       xstr = 1;  }

        // layer 0
        step_layer(smb, bx, by, tid, warp, lane, cur, (const __half*)nullptr, W0, HH,
                   B0, w0, xs, xstr, g_c0, nxt, true, false, nullptr);
        group_barrier(bx, gen);

        // layer 1 (+ FC partials in decoder)
        step_layer(smb, bx, by, tid, warp, lane, nxt, cur + HH, W1, 2*HH,
                   B1, nullptr, nullptr, 0, g_c1, nxt + HH, false, dec, fcW);
        group_barrier(bx, gen);

        if (dec){
            if (by == 0 && tid < BM){
                const int m = bx * BM + tid;
                float s = fcb[0];
                #pragma unroll
                for (int p = 0; p < 64; p++) s += g_predPart[p*BB + m];
                g_pred[m] = s;
                out[(size_t)m*TT + (t - SS)] = s;
            }
            group_barrier(bx, gen);
        }

        __half* tmp = cur; cur = nxt; nxt = tmp;
    }
}

// ---------------- host: one launch, one graph node ----------------
extern "C" void kernel_launch(void* const* d_in, const int* in_sizes, int n_in,
                              void* d_out, int out_size)
{
    cudaFuncSetAttribute((const void*)seq2seq_persistent,
                         cudaFuncAttributeMaxDynamicSharedMemorySize, SMEM_DYN);

    seq2seq_persistent<<<NBLK, NTHR, SMEM_DYN>>>(
        (const float*)d_in[0],
        (const float*)d_in[1],  (const float*)d_in[2],
        (const float*)d_in[3],  (const float*)d_in[4],
        (const float*)d_in[5],  (const float*)d_in[6],
        (const float*)d_in[7],  (const float*)d_in[8],
        (const float*)d_in[9],  (const float*)d_in[10],
        (const float*)d_in[11], (const float*)d_in[12],
        (const float*)d_in[13], (const float*)d_in[14],
        (const float*)d_in[15], (const float*)d_in[16],
        (const float*)d_in[17], (const float*)d_in[18],
        (float*)d_out);
    (void)in_sizes; (void)n_in; (void)out_size;
}

// round 12
// speedup vs baseline: 1.1726x; 1.0516x over previous
#include <cuda_runtime.h>
#include <cuda_fp16.h>
#include <cstdint>

#define BB 2048
#define SS 288
#define HH 512
#define TT 144
#define G4 (4*HH)

#define NBLK 128
#define NTHR 512
#define BM 128
#define BNJ 64          // j-cols per block
#define BK 64
#define NGRP 16         // M-row groups
#define GBLK 8          // blocks per group (N-partition)

#define STG_A_SZ (BM*128)            // 16 KB
#define STG_B_SZ (256*128)           // 32 KB
#define STG_SZ   (STG_A_SZ+STG_B_SZ) // 48 KB
#define SMEM_DYN (3*STG_SZ + 1024)

#define SW128(x) ((x) ^ (((x) >> 3) & 0x70))

// ---------------- device state (static; no runtime allocation) ----------------
__device__ __align__(128) __half g_hA[BB*1024];       // [h0 | h1] ping
__device__ __align__(128) __half g_hB[BB*1024];       // [h0 | h1] pong
__device__ __align__(128) float  g_c0[BB*HH];
__device__ __align__(128) float  g_c1[BB*HH];
__device__ __align__(128) float  g_pred[BB];
__device__ __align__(128) float  g_predPart[64*BB];
__device__ __align__(128) __half g_encW0[G4*HH];
__device__ __align__(128) __half g_encW1[G4*2*HH];
__device__ __align__(128) __half g_decW0[G4*HH];
__device__ __align__(128) __half g_decW1[G4*2*HH];
__device__ __align__(128) float  g_encB0[G4];
__device__ __align__(128) float  g_encB1[G4];
__device__ __align__(128) float  g_decB0[G4];
__device__ __align__(128) float  g_decB1[G4];
__device__ unsigned g_grpCnt[NGRP];
__device__ unsigned g_grpGen[NGRP];
__device__ unsigned g_barCnt;
__device__ unsigned g_barGen;

// ---------------- barriers ----------------
__device__ __forceinline__ void group_barrier(int grp, unsigned &gen){
    __threadfence();
    __syncthreads();
    if (threadIdx.x == 0){
        unsigned prev = atomicAdd(&g_grpCnt[grp], 1u);
        if (prev == GBLK - 1u){
            *(volatile unsigned*)&g_grpCnt[grp] = 0u;
            __threadfence();
            *(volatile unsigned*)&g_grpGen[grp] = gen + 1u;
        } else {
            while (*(volatile unsigned*)&g_grpGen[grp] == gen) __nanosleep(32);
        }
    }
    __syncthreads();
    __threadfence();
    gen++;
}
__device__ __forceinline__ void grid_barrier(unsigned &gen){
    __threadfence();
    __syncthreads();
    if (threadIdx.x == 0){
        unsigned prev = atomicAdd(&g_barCnt, 1u);
        if (prev == NBLK - 1u){
            *(volatile unsigned*)&g_barCnt = 0u;
            __threadfence();
            *(volatile unsigned*)&g_barGen = gen + 1u;
        } else {
            while (*(volatile unsigned*)&g_barGen == gen) __nanosleep(64);
        }
    }
    __syncthreads();
    __threadfence();
    gen++;
}

// ---------------- helpers ----------------
__device__ __forceinline__ void cp16(unsigned d, const void* s){
    asm volatile("cp.async.cg.shared.global [%0], [%1], 16;\n" :: "r"(d), "l"(s));
}
__device__ __forceinline__ void cp_commit(){ asm volatile("cp.async.commit_group;\n"); }
__device__ __forceinline__ void cp_wait1(){ asm volatile("cp.async.wait_group 1;\n"); }
__device__ __forceinline__ void cp_wait0(){ asm volatile("cp.async.wait_group 0;\n"); }

__device__ __forceinline__ void ldsm_x4(unsigned* r, const void* p){
    unsigned a = (unsigned)__cvta_generic_to_shared(p);
    asm volatile("ldmatrix.sync.aligned.m8n8.x4.shared.b16 {%0,%1,%2,%3}, [%4];\n"
        : "=r"(r[0]), "=r"(r[1]), "=r"(r[2]), "=r"(r[3]) : "r"(a));
}
__device__ __forceinline__ void mma16816(float* d, const unsigned* a, unsigned b0, unsigned b1){
    asm volatile(
        "mma.sync.aligned.m16n8k16.row.col.f32.f16.f16.f32 "
        "{%0,%1,%2,%3}, {%4,%5,%6,%7}, {%8,%9}, {%0,%1,%2,%3};\n"
        : "+f"(d[0]), "+f"(d[1]), "+f"(d[2]), "+f"(d[3])
        : "r"(a[0]), "r"(a[1]), "r"(a[2]), "r"(a[3]), "r"(b0), "r"(b1));
}

// ---- fast activations: single-MUFU tanh (sm_75+) ----
__device__ __forceinline__ float tanh_fast(float x){
    float y;
    asm("tanh.approx.f32 %0, %1;\n" : "=f"(y) : "f"(x));
    return y;
}
__device__ __forceinline__ float sig_fast(float x){
    return fmaf(tanh_fast(0.5f * x), 0.5f, 0.5f);
}

// ---------------- one fused GEMM + LSTM-cell phase ----------------
// B smem row n (0..255):  wjIdx = n>>5, gate = (n>>3)&3, jo = n&7
//   <- W row  gate*HH + jBase + wjIdx*8 + jo
// 16 warps: warp&1 = M half (64 rows via 4 m-tiles), warp>>1 = N-strip
// (8 strips of 32 = 4 gates x 8 j). Each thread owns all 4 gates of its j's.
__device__ void step_layer(char* smb, int bx, int by, int tid, int warp, int lane,
    const __half* __restrict__ A0, const __half* __restrict__ A1,
    const __half* __restrict__ W, int K,
    const float* __restrict__ bias, const float* __restrict__ w0,
    const float* __restrict__ xsrc, int xstride,
    float* __restrict__ cbuf, __half* __restrict__ hOut,
    bool hasX, bool doFC, const float* __restrict__ fcW)
{
    const int gmBase = bx * BM;
    const int jBase  = by * BNJ;
    const int nT = K / BK;

    float acc[4][4][4];   // [mt][gate][r]
    #pragma unroll
    for (int a = 0; a < 4; a++)
        #pragma unroll
        for (int g = 0; g < 4; g++)
            #pragma unroll
            for (int r = 0; r < 4; r++) acc[a][g][r] = 0.f;

    const int wm    = (warp & 1) * 64;     // 2 warps over M=128 (64 rows each)
    const int wjIdx = warp >> 1;           // 8 warps over N=256 (8 j's each)
    const int lr = lane >> 2;
    const int lc = lane & 3;

    const int l8  = lane & 7;
    const int seg = lane >> 3;
    const int aRowOff = ((seg & 1) ? 8 : 0) + l8;   // A regs: (m0,k0),(m8,k0),(m0,k8),(m8,k8)
    const int aColOff = (seg >> 1) ? 8 : 0;
    const int bRowOff = ((seg >> 1) ? 8 : 0) + l8;  // B regs: (n0,k0),(n0,k8),(n8,k0),(n8,k8)
    const int bColOff = (seg & 1) ? 8 : 0;

    auto issue = [&](int tt){
        const int s = tt % 3;
        const unsigned stA = (unsigned)__cvta_generic_to_shared(smb + s*STG_SZ);
        const unsigned stB = stA + STG_A_SZ;
        const int kk = tt * BK;
        const __half* Ap = (kk < HH) ? (A0 + kk) : (A1 + (kk - HH));
        #pragma unroll
        for (int i = 0; i < 2; i++){   // A: 128 rows x 128B, 2 cp16/thread
            const int q = tid + i*NTHR;
            const int r = q >> 3, cc = q & 7;
            cp16(stA + SW128(r*128 + cc*16), Ap + (size_t)(gmBase + r)*1024 + cc*8);
        }
        #pragma unroll
        for (int i = 0; i < 4; i++){   // B: 256 rows x 128B, 4 cp16/thread
            const int q = tid + i*NTHR;
            const int r = q >> 3, cc = q & 7;
            const int wr = ((r >> 3) & 3)*HH + jBase + ((r >> 5) << 3) + (r & 7);
            cp16(stB + SW128(r*128 + cc*16), W + (size_t)wr*K + kk + cc*8);
        }
        cp_commit();
    };

    issue(0);
    issue(1);
    for (int tt = 0; tt < nT; tt++){
        if (tt + 2 < nT) cp_wait1(); else cp_wait0();
        __syncthreads();
        if (tt + 2 < nT) issue(tt + 2);
        const int s = tt % 3;
        const char* Ab = smb + s*STG_SZ;
        const char* Bb = smb + s*STG_SZ + STG_A_SZ;
        #pragma unroll
        for (int ks = 0; ks < 4; ks++){
            const int kb = ks * 16;
            unsigned a[4][4];
            #pragma unroll
            for (int mt = 0; mt < 4; mt++){
                const unsigned off = SW128((unsigned)((wm + mt*16 + aRowOff)*128 + (kb + aColOff)*2));
                ldsm_x4(a[mt], Ab + off);
            }
            unsigned bl[4], bh[4];
            {
                const unsigned offL = SW128((unsigned)((wjIdx*32 + bRowOff)*128 + (kb + bColOff)*2));
                const unsigned offH = SW128((unsigned)((wjIdx*32 + 16 + bRowOff)*128 + (kb + bColOff)*2));
                ldsm_x4(bl, Bb + offL);
                ldsm_x4(bh, Bb + offH);
            }
            #pragma unroll
            for (int mt = 0; mt < 4; mt++){
                mma16816(acc[mt][0], a[mt], bl[0], bl[1]);
                mma16816(acc[mt][1], a[mt], bl[2], bl[3]);
                mma16816(acc[mt][2], a[mt], bh[0], bh[1]);
                mma16816(acc[mt][3], a[mt], bh[2], bh[3]);
            }
        }
    }
    __syncthreads();   // protect smem before next phase reuses it

    // ------- fused LSTM epilogue (tanh.approx activations) -------
    const int j0 = jBase + wjIdx*8;
    float fcs[8] = {0.f, 0.f, 0.f, 0.f, 0.f, 0.f, 0.f, 0.f};
    #pragma unroll
    for (int mt = 0; mt < 4; mt++){
        #pragma unroll
        for (int rr = 0; rr < 2; rr++){
            const int m = gmBase + wm + mt*16 + lr + rr*8;
            const float xval = hasX ? xsrc[(size_t)m * xstride] : 0.f;
            #pragma unroll
            for (int jj = 0; jj < 2; jj++){
                const int j = j0 + 2*lc + jj;
                const int r = rr*2 + jj;
                float gi = acc[mt][0][r] + bias[j];
                float gf = acc[mt][1][r] + bias[HH + j];
                float gg = acc[mt][2][r] + bias[2*HH + j];
                float go = acc[mt][3][r] + bias[3*HH + j];
                if (hasX){
                    gi += xval * w0[j];
                    gf += xval * w0[HH + j];
                    gg += xval * w0[2*HH + j];
                    go += xval * w0[3*HH + j];
                }
                const float c  = cbuf[(size_t)m*HH + j];
                const float cn = sig_fast(gf)*c + sig_fast(gi)*tanh_fast(gg);
                const float hn = sig_fast(go)*tanh_fast(cn);
                cbuf[(size_t)m*HH + j] = cn;
                hOut[(size_t)m*1024 + j] = __float2half(hn);
                if (doFC) fcs[mt*2 + rr] += hn * fcW[j];
            }
        }
    }
    if (doFC){
        #pragma unroll
        for (int i = 0; i < 8; i++){
            fcs[i] += __shfl_xor_sync(0xffffffffu, fcs[i], 1);
            fcs[i] += __shfl_xor_sync(0xffffffffu, fcs[i], 2);
        }
        if (lc == 0){
            const int partIdx = by*8 + wjIdx;       // 64 partials per row
            #pragma unroll
            for (int i = 0; i < 8; i++){
                const int m = gmBase + wm + (i >> 1)*16 + lr + ((i & 1) ? 8 : 0);
                g_predPart[partIdx*BB + m] = fcs[i];
            }
        }
    }
}

// ---------------- the single persistent kernel ----------------
__global__ void __launch_bounds__(NTHR, 1)
seq2seq_persistent(const float* __restrict__ x,
    const float* __restrict__ eWih0, const float* __restrict__ eWhh0,
    const float* __restrict__ ebih0, const float* __restrict__ ebhh0,
    const float* __restrict__ eWih1, const float* __restrict__ eWhh1,
    const float* __restrict__ ebih1, const float* __restrict__ ebhh1,
    const float* __restrict__ dWih0, const float* __restrict__ dWhh0,
    const float* __restrict__ dbih0, const float* __restrict__ dbhh0,
    const float* __restrict__ dWih1, const float* __restrict__ dWhh1,
    const float* __restrict__ dbih1, const float* __restrict__ dbhh1,
    const float* __restrict__ fcW,  const float* __restrict__ fcb,
    float* __restrict__ out)
{
    extern __shared__ char smraw[];
    char* smb = (char*)(((uintptr_t)smraw + 1023) & ~(uintptr_t)1023);

    const int tid  = threadIdx.x;
    const int warp = tid >> 5;
    const int lane = tid & 31;
    const int blk  = blockIdx.x;
    const int bx   = blk & 15;          // M-group (16 of 128 rows)
    const int by   = blk >> 4;          // N-partition within group (8 of 64 j)
    const int gtid = blk * NTHR + tid;
    const int NT   = NBLK * NTHR;

    unsigned ggen = *(volatile unsigned*)&g_barGen;

    // ---- prep: zero state, pack weights to fp16, combine biases ----
    for (int i = gtid; i < BB*1024; i += NT) g_hA[i] = __float2half(0.f);
    for (int i = gtid; i < BB*HH; i += NT){ g_c0[i] = 0.f; g_c1[i] = 0.f; }
    for (int i = gtid; i < G4*HH; i += NT){
        g_encW0[i] = __float2half(eWhh0[i]);
        g_decW0[i] = __float2half(dWhh0[i]);
    }
    for (int i = gtid; i < G4*1024; i += NT){
        const int n = i >> 10, k = i & 1023;
        g_encW1[i] = __float2half((k < HH) ? eWih1[n*HH + k] : eWhh1[n*HH + k - HH]);
        g_decW1[i] = __float2half((k < HH) ? dWih1[n*HH + k] : dWhh1[n*HH + k - HH]);
    }
    if (gtid < G4){
        g_encB0[gtid] = ebih0[gtid] + ebhh0[gtid];
        g_encB1[gtid] = ebih1[gtid] + ebhh1[gtid];
        g_decB0[gtid] = dbih0[gtid] + dbhh0[gtid];
        g_decB1[gtid] = dbih1[gtid] + dbhh1[gtid];
    }
    grid_barrier(ggen);

    unsigned gen = *(volatile unsigned*)&g_grpGen[bx];

    __half* cur = g_hA;
    __half* nxt = g_hB;

    for (int t = 0; t < SS + TT; t++){
        const bool dec = (t >= SS);
        const __half* W0 = dec ? g_decW0 : g_encW0;
        const __half* W1 = dec ? g_decW1 : g_encW1;
        const float* B0  = dec ? g_decB0 : g_encB0;
        const float* B1  = dec ? g_decB1 : g_encB1;
        const float* w0  = dec ? dWih0 : eWih0;

        const float* xs;
        int xstr;
        if (!dec)          { xs = x + t;        xstr = SS; }
        else if (t == SS)  { xs = x + (SS - 1); xstr = SS; }
        else               { xs = g_pred;       xstr = 1;  }

        // layer 0
        step_layer(smb, bx, by, tid, warp, lane, cur, (const __half*)nullptr, W0, HH,
                   B0, w0, xs, xstr, g_c0, nxt, true, false, nullptr);
        group_barrier(bx, gen);

        // layer 1 (+ FC partials in decoder)
        step_layer(smb, bx, by, tid, warp, lane, nxt, cur + HH, W1, 2*HH,
                   B1, nullptr, nullptr, 0, g_c1, nxt + HH, false, dec, fcW);
        group_barrier(bx, gen);

        if (dec){
            if (by == 0 && tid < BM){
                const int m = bx * BM + tid;
                float s = fcb[0];
                #pragma unroll
                for (int p = 0; p < 64; p++) s += g_predPart[p*BB + m];
                g_pred[m] = s;
                out[(size_t)m*TT + (t - SS)] = s;
            }
            group_barrier(bx, gen);
        }

        __half* tmp = cur; cur = nxt; nxt = tmp;
    }
}

// ---------------- host: one launch, one graph node ----------------
extern "C" void kernel_launch(void* const* d_in, const int* in_sizes, int n_in,
                              void* d_out, int out_size)
{
    cudaFuncSetAttribute((const void*)seq2seq_persistent,
                         cudaFuncAttributeMaxDynamicSharedMemorySize, SMEM_DYN);

    seq2seq_persistent<<<NBLK, NTHR, SMEM_DYN>>>(
        (const float*)d_in[0],
        (const float*)d_in[1],  (const float*)d_in[2],
        (const float*)d_in[3],  (const float*)d_in[4],
        (const float*)d_in[5],  (const float*)d_in[6],
        (const float*)d_in[7],  (const float*)d_in[8],
        (const float*)d_in[9],  (const float*)d_in[10],
        (const float*)d_in[11], (const float*)d_in[12],
        (const float*)d_in[13], (const float*)d_in[14],
        (const float*)d_in[15], (const float*)d_in[16],
        (const float*)d_in[17], (const float*)d_in[18],
        (float*)d_out);
    (void)in_sizes; (void)n_in; (void)out_size;
}